// round 1
// baseline (speedup 1.0000x reference)
#include <cuda_runtime.h>
#include <cuda_bf16.h>
#include <cstdint>
#include <math.h>

#define D_  1024
#define V_  50257
#define B_  2
#define S_  2048
#define S1_ 2049
#define T_  4096
#define NCHUNK 32
#define CLEN   64

// ---------------- scratch (static device globals; no runtime allocation) ----
__device__ float g_h1[(size_t)T_ * D_];
__device__ float g_hg[(size_t)T_ * 2 * D_];
__device__ float g_cb[(size_t)T_ * D_];
__device__ float g_vb[(size_t)T_ * D_];
__device__ float g_Ac[B_ * NCHUNK * D_];
__device__ float g_Bc[B_ * NCHUNK * D_];
__device__ float g_carry[B_ * NCHUNK * D_];
__device__ float g_h2[(size_t)T_ * D_];
__device__ float g_mlp1[(size_t)T_ * 4 * D_];
__device__ float g_h3[(size_t)T_ * D_];
__device__ float g_h4[(size_t)T_ * D_];
__device__ float g_lp[T_];

// ---------------- helpers ---------------------------------------------------
__device__ __forceinline__ float to_tf32(float x) {
    uint32_t u;
    asm("cvt.rna.tf32.f32 %0, %1;" : "=r"(u) : "f"(x));
    return __uint_as_float(u);
}

__device__ __forceinline__ void mma_tf32(float c[4], const uint32_t a[4], const uint32_t b[2]) {
    asm volatile(
        "mma.sync.aligned.m16n8k8.row.col.f32.tf32.tf32.f32 "
        "{%0,%1,%2,%3}, {%4,%5,%6,%7}, {%8,%9}, {%0,%1,%2,%3};"
        : "+f"(c[0]), "+f"(c[1]), "+f"(c[2]), "+f"(c[3])
        : "r"(a[0]), "r"(a[1]), "r"(a[2]), "r"(a[3]), "r"(b[0]), "r"(b[1]));
}

__device__ __forceinline__ float gelu_exact(float x) {
    return 0.5f * x * (1.0f + erff(x * 0.7071067811865476f));
}

// ---------------- GEMM: C[M,N] = A[M,K] @ B[K,N] (+bias, gelu, +resid) ------
// tf32 tensor cores. CTA tile 128x128, BK=32, 256 threads = 8 warps (2x4),
// warp tile 64x32 via m16n8k8 fragments. SMEM strides 36/136 => conflict-free
// fragment loads. blockIdx.x = M tile (so co-resident CTAs share B strip in L2).
#define BM 128
#define BN 128
#define BK 32
#define ASTR 36
#define BSTR 136

__global__ __launch_bounds__(256, 1)
void gemm_tf32(const float* __restrict__ A, const float* __restrict__ B,
               float* __restrict__ C, int M, int N, int K,
               const float* __restrict__ bias, const float* __restrict__ resid,
               int do_gelu)
{
    __shared__ __align__(16) float As[BM * ASTR];
    __shared__ __align__(16) float Bs[BK * BSTR];

    const int tid  = threadIdx.x;
    const int lane = tid & 31;
    const int warp = tid >> 5;
    const int wm   = warp >> 2;      // 0..1
    const int wn   = warp & 3;       // 0..3
    const int g    = lane >> 2;      // 0..7
    const int tg   = lane & 3;       // 0..3

    const int m0 = blockIdx.x * BM;
    const int n0 = blockIdx.y * BN;

    float acc[4][4][4];
    #pragma unroll
    for (int mi = 0; mi < 4; mi++)
        #pragma unroll
        for (int ni = 0; ni < 4; ni++)
            #pragma unroll
            for (int r = 0; r < 4; r++) acc[mi][ni][r] = 0.f;

    const int ar  = tid >> 3;          // 0..31  (A row within pass)
    const int akk = (tid & 7) * 4;     // 0..28
    const int bkr = tid >> 5;          // 0..7   (B k-row within pass)
    const int bnc = (tid & 31) * 4;    // 0..124

    for (int kt = 0; kt < K; kt += BK) {
        __syncthreads();
        // --- load A tile (vectorized; M,K multiples of 128/32 always) ---
        #pragma unroll
        for (int p = 0; p < 4; p++) {
            int row = ar + p * 32;
            float4 av = *(const float4*)(A + (size_t)(m0 + row) * K + kt + akk);
            float4 o;
            o.x = to_tf32(av.x); o.y = to_tf32(av.y);
            o.z = to_tf32(av.z); o.w = to_tf32(av.w);
            *(float4*)(As + row * ASTR + akk) = o;
        }
        // --- load B tile (scalar + guard: N may be 50257) ---
        #pragma unroll
        for (int p = 0; p < 4; p++) {
            int kk = bkr + p * 8;
            const float* brow = B + (size_t)(kt + kk) * N;
            #pragma unroll
            for (int j = 0; j < 4; j++) {
                int n = n0 + bnc + j;
                float v = (n < N) ? brow[n] : 0.f;
                Bs[kk * BSTR + bnc + j] = to_tf32(v);
            }
        }
        __syncthreads();

        #pragma unroll
        for (int kc = 0; kc < 4; kc++) {
            uint32_t af[4][4], bf[4][2];
            #pragma unroll
            for (int mi = 0; mi < 4; mi++) {
                int mb = wm * 64 + mi * 16;
                af[mi][0] = __float_as_uint(As[(mb + g)     * ASTR + kc * 8 + tg]);
                af[mi][1] = __float_as_uint(As[(mb + g + 8) * ASTR + kc * 8 + tg]);
                af[mi][2] = __float_as_uint(As[(mb + g)     * ASTR + kc * 8 + tg + 4]);
                af[mi][3] = __float_as_uint(As[(mb + g + 8) * ASTR + kc * 8 + tg + 4]);
            }
            #pragma unroll
            for (int ni = 0; ni < 4; ni++) {
                int nb = wn * 32 + ni * 8;
                bf[ni][0] = __float_as_uint(Bs[(kc * 8 + tg)     * BSTR + nb + g]);
                bf[ni][1] = __float_as_uint(Bs[(kc * 8 + tg + 4) * BSTR + nb + g]);
            }
            #pragma unroll
            for (int mi = 0; mi < 4; mi++)
                #pragma unroll
                for (int ni = 0; ni < 4; ni++)
                    mma_tf32(acc[mi][ni], af[mi], bf[ni]);
        }
    }

    // --- epilogue ---
    #pragma unroll
    for (int mi = 0; mi < 4; mi++) {
        int row0 = m0 + wm * 64 + mi * 16 + g;
        #pragma unroll
        for (int ni = 0; ni < 4; ni++) {
            int col = n0 + wn * 32 + ni * 8 + tg * 2;
            #pragma unroll
            for (int rr = 0; rr < 2; rr++) {
                int row = row0 + rr * 8;
                float v0 = acc[mi][ni][rr * 2 + 0];
                float v1 = acc[mi][ni][rr * 2 + 1];
                if (col < N) {
                    float o0 = v0;
                    if (bias)   o0 += bias[col];
                    if (do_gelu) o0 = gelu_exact(o0);
                    if (resid)  o0 += resid[(size_t)row * N + col];
                    C[(size_t)row * N + col] = o0;
                }
                if (col + 1 < N) {
                    float o1 = v1;
                    if (bias)   o1 += bias[col + 1];
                    if (do_gelu) o1 = gelu_exact(o1);
                    if (resid)  o1 += resid[(size_t)row * N + col + 1];
                    C[(size_t)row * N + col + 1] = o1;
                }
            }
        }
    }
}

// ---------------- embedding gather + RMSNorm --------------------------------
__global__ void embed_rms(const int* __restrict__ x, const float* __restrict__ emb,
                          const float* __restrict__ gamma, float* __restrict__ h1)
{
    int tk = blockIdx.x;
    int b = tk >> 11, t = tk & 2047;
    int id = x[b * S1_ + t];
    const float4* row = (const float4*)(emb + (size_t)id * D_);
    int tid = threadIdx.x;
    float4 v = row[tid];
    float ss = v.x * v.x + v.y * v.y + v.z * v.z + v.w * v.w;
    __shared__ float red[256];
    red[tid] = ss; __syncthreads();
    for (int st = 128; st > 0; st >>= 1) {
        if (tid < st) red[tid] += red[tid + st];
        __syncthreads();
    }
    float scale = 32.0f / fmaxf(sqrtf(red[0]), 1e-12f);
    float4 gv = ((const float4*)gamma)[tid];
    float4 o;
    o.x = v.x * scale * (gv.x + 1.f); o.y = v.y * scale * (gv.y + 1.f);
    o.z = v.z * scale * (gv.z + 1.f); o.w = v.w * scale * (gv.w + 1.f);
    ((float4*)(h1 + (size_t)tk * D_))[tid] = o;
}

__global__ void rms_rows(const float* __restrict__ in, const float* __restrict__ gamma,
                         float* __restrict__ outp)
{
    int tk = blockIdx.x;
    int tid = threadIdx.x;
    float4 v = ((const float4*)(in + (size_t)tk * D_))[tid];
    float ss = v.x * v.x + v.y * v.y + v.z * v.z + v.w * v.w;
    __shared__ float red[256];
    red[tid] = ss; __syncthreads();
    for (int st = 128; st > 0; st >>= 1) {
        if (tid < st) red[tid] += red[tid + st];
        __syncthreads();
    }
    float scale = 32.0f / fmaxf(sqrtf(red[0]), 1e-12f);
    float4 gv = ((const float4*)gamma)[tid];
    float4 o;
    o.x = v.x * scale * (gv.x + 1.f); o.y = v.y * scale * (gv.y + 1.f);
    o.z = v.z * scale * (gv.z + 1.f); o.w = v.w * scale * (gv.w + 1.f);
    ((float4*)(outp + (size_t)tk * D_))[tid] = o;
}

// ---------------- minGRU chunked linear-recurrence scan ---------------------
// h_t = c_t*h_{t-1} + v_t,  c=sigmoid(-gate), v=sigmoid(gate)*g(hidden)
// g(x) = x+0.5 (x>=0), sigmoid(x) (x<0).   h_{-1} = 0.
__global__ void scan_phase1(const float* __restrict__ hg, float* __restrict__ cb,
                            float* __restrict__ vb, float* __restrict__ Ac,
                            float* __restrict__ Bc)
{
    int gt = blockIdx.x * blockDim.x + threadIdx.x;      // B*NCHUNK*D threads
    int d = gt & (D_ - 1);
    int chunk = (gt >> 10) & (NCHUNK - 1);
    int b = gt >> 15;
    float Aacc = 1.f, Bacc = 0.f;
    for (int s = 0; s < CLEN; s++) {
        int t = chunk * CLEN + s;
        size_t row = (size_t)(b * S_ + t) * (2 * D_);
        float hid  = hg[row + d];
        float gate = hg[row + D_ + d];
        float c = 1.f / (1.f + expf(gate));              // sigmoid(-gate)
        float z = 1.f / (1.f + expf(-gate));             // sigmoid(gate)
        float gg = (hid >= 0.f) ? (hid + 0.5f) : (1.f / (1.f + expf(-hid)));
        float v = z * gg;
        size_t o = (size_t)(b * S_ + t) * D_ + d;
        cb[o] = c; vb[o] = v;
        Bacc = c * Bacc + v;
        Aacc *= c;
    }
    int idx = (b * NCHUNK + chunk) * D_ + d;
    Ac[idx] = Aacc; Bc[idx] = Bacc;
}

__global__ void scan_phase2(const float* __restrict__ Ac, const float* __restrict__ Bc,
                            float* __restrict__ carry)
{
    int gt = blockIdx.x * blockDim.x + threadIdx.x;      // B*D threads
    int d = gt & (D_ - 1);
    int b = gt >> 10;
    float h = 0.f;
    for (int chunk = 0; chunk < NCHUNK; chunk++) {
        int idx = (b * NCHUNK + chunk) * D_ + d;
        carry[idx] = h;
        h = Ac[idx] * h + Bc[idx];
    }
}

__global__ void scan_phase3(const float* __restrict__ cb, const float* __restrict__ vb,
                            const float* __restrict__ carry, const float* __restrict__ h1,
                            float* __restrict__ h2, float* __restrict__ next_hidden)
{
    int gt = blockIdx.x * blockDim.x + threadIdx.x;
    int d = gt & (D_ - 1);
    int chunk = (gt >> 10) & (NCHUNK - 1);
    int b = gt >> 15;
    float h = carry[(b * NCHUNK + chunk) * D_ + d];
    for (int s = 0; s < CLEN; s++) {
        int t = chunk * CLEN + s;
        size_t o = (size_t)(b * S_ + t) * D_ + d;
        h = cb[o] * h + vb[o];
        h2[o] = h + h1[o];
        if (t == S_ - 1) next_hidden[b * D_ + d] = h;
    }
}

// ---------------- loss: per-row logsumexp + gather, then mean ---------------
__global__ void loss_rows(const float* __restrict__ logits, const int* __restrict__ x,
                          float* __restrict__ lp)
{
    int tk = blockIdx.x;
    int tid = threadIdx.x;
    const float* row = logits + (size_t)tk * V_;
    float m = -INFINITY, s = 0.f;
    for (int i = tid; i < V_; i += 256) {
        float v = row[i];
        if (v > m) { s = s * expf(m - v) + 1.f; m = v; }
        else       { s += expf(v - m); }
    }
    __shared__ float sm[256], ssum[256];
    sm[tid] = m; ssum[tid] = s; __syncthreads();
    for (int st = 128; st > 0; st >>= 1) {
        if (tid < st) {
            float m2 = sm[tid + st], s2 = ssum[tid + st];
            float M = fmaxf(sm[tid], m2);
            ssum[tid] = ssum[tid] * expf(sm[tid] - M) + s2 * expf(m2 - M);
            sm[tid] = M;
        }
        __syncthreads();
    }
    if (tid == 0) {
        int b = tk >> 11, t = tk & 2047;
        int lab = x[b * S1_ + t + 1];
        lp[tk] = row[lab] - (sm[0] + logf(ssum[0]));
    }
}

__global__ void loss_final(const float* __restrict__ lp, float* __restrict__ outp)
{
    int tid = threadIdx.x;
    float s = 0.f;
    for (int i = tid; i < T_; i += 256) s += lp[i];
    __shared__ float red[256];
    red[tid] = s; __syncthreads();
    for (int st = 128; st > 0; st >>= 1) {
        if (tid < st) red[tid] += red[tid + st];
        __syncthreads();
    }
    if (tid == 0) outp[0] = -red[0] / (float)T_;
}

// ---------------- launch ----------------------------------------------------
extern "C" void kernel_launch(void* const* d_in, const int* in_sizes, int n_in,
                              void* d_out, int out_size)
{
    const int*   x       = (const int*)  d_in[0];
    const float* emb     = (const float*)d_in[1];
    const float* gamma1  = (const float*)d_in[2];
    const float* W_hg    = (const float*)d_in[3];
    const float* W1      = (const float*)d_in[4];
    const float* b1      = (const float*)d_in[5];
    const float* W2      = (const float*)d_in[6];
    const float* b2      = (const float*)d_in[7];
    const float* gamma2  = (const float*)d_in[8];
    const float* Wlog    = (const float*)d_in[9];
    float* out = (float*)d_out;

    float *h1, *hg, *cb, *vb, *Ac, *Bc, *carry, *h2, *mlp1, *h3, *h4, *lp;
    cudaGetSymbolAddress((void**)&h1,    g_h1);
    cudaGetSymbolAddress((void**)&hg,    g_hg);
    cudaGetSymbolAddress((void**)&cb,    g_cb);
    cudaGetSymbolAddress((void**)&vb,    g_vb);
    cudaGetSymbolAddress((void**)&Ac,    g_Ac);
    cudaGetSymbolAddress((void**)&Bc,    g_Bc);
    cudaGetSymbolAddress((void**)&carry, g_carry);
    cudaGetSymbolAddress((void**)&h2,    g_h2);
    cudaGetSymbolAddress((void**)&mlp1,  g_mlp1);
    cudaGetSymbolAddress((void**)&h3,    g_h3);
    cudaGetSymbolAddress((void**)&h4,    g_h4);
    cudaGetSymbolAddress((void**)&lp,    g_lp);

    float* logits      = out + 1;
    float* next_hidden = out + 1 + (size_t)T_ * V_;

    embed_rms<<<T_, 256>>>(x, emb, gamma1, h1);

    // hg = h1 @ W_hg   [4096 x 2048]
    gemm_tf32<<<dim3(T_ / BM, (2 * D_) / BN), 256>>>(
        h1, W_hg, hg, T_, 2 * D_, D_, nullptr, nullptr, 0);

    scan_phase1<<<(B_ * NCHUNK * D_) / 256, 256>>>(hg, cb, vb, Ac, Bc);
    scan_phase2<<<(B_ * D_) / 256, 256>>>(Ac, Bc, carry);
    scan_phase3<<<(B_ * NCHUNK * D_) / 256, 256>>>(cb, vb, carry, h1, h2, next_hidden);

    // mlp1 = gelu(h2 @ W1 + b1)   [4096 x 4096]
    gemm_tf32<<<dim3(T_ / BM, (4 * D_) / BN), 256>>>(
        h2, W1, mlp1, T_, 4 * D_, D_, b1, nullptr, 1);

    // h3 = mlp1 @ W2 + b2 + h2    [4096 x 1024]
    gemm_tf32<<<dim3(T_ / BM, D_ / BN), 256>>>(
        mlp1, W2, h3, T_, D_, 4 * D_, b2, h2, 0);

    rms_rows<<<T_, 256>>>(h3, gamma2, h4);

    // logits = h4 @ W_logits      [4096 x 50257]
    gemm_tf32<<<dim3(T_ / BM, (V_ + BN - 1) / BN), 256>>>(
        h4, Wlog, logits, T_, V_, D_, nullptr, nullptr, 0);

    loss_rows<<<T_, 256>>>(logits, x, lp);
    loss_final<<<1, 256>>>(lp, out);
}

// round 2
// speedup vs baseline: 1.4286x; 1.4286x over previous
#include <cuda_runtime.h>
#include <cuda_bf16.h>
#include <cstdint>
#include <math.h>

#define D_  1024
#define V_  50257
#define VP_ 50304          // V padded to multiple of 128
#define B_  2
#define S_  2048
#define S1_ 2049
#define T_  4096
#define NCHUNK 32
#define CLEN   64

// ---------------- scratch (static device globals; no runtime allocation) ----
__device__ float g_h1[(size_t)T_ * D_];
__device__ float g_hg[(size_t)T_ * 2 * D_];
__device__ float g_cb[(size_t)T_ * D_];
__device__ float g_vb[(size_t)T_ * D_];
__device__ float g_Ac[B_ * NCHUNK * D_];
__device__ float g_Bc[B_ * NCHUNK * D_];
__device__ float g_carry[B_ * NCHUNK * D_];
__device__ float g_h2[(size_t)T_ * D_];
__device__ float g_mlp1[(size_t)T_ * 4 * D_];
__device__ float g_h3[(size_t)T_ * D_];
__device__ float g_h4[(size_t)T_ * D_];
__device__ float g_lp[T_];
// transposed (N-major) tf32-rounded weights
__device__ float g_whgT[(size_t)(2 * D_) * D_];
__device__ float g_w1T [(size_t)(4 * D_) * D_];
__device__ float g_w2T [(size_t)D_ * (4 * D_)];
__device__ float g_wlogT[(size_t)VP_ * D_];

// ---------------- helpers ---------------------------------------------------
__device__ __forceinline__ float to_tf32(float x) {
    uint32_t u;
    asm("cvt.rna.tf32.f32 %0, %1;" : "=r"(u) : "f"(x));
    return __uint_as_float(u);
}

__device__ __forceinline__ void mma_tf32(float c[4], const uint32_t a[4], const uint32_t b[2]) {
    asm volatile(
        "mma.sync.aligned.m16n8k8.row.col.f32.tf32.tf32.f32 "
        "{%0,%1,%2,%3}, {%4,%5,%6,%7}, {%8,%9}, {%0,%1,%2,%3};"
        : "+f"(c[0]), "+f"(c[1]), "+f"(c[2]), "+f"(c[3])
        : "r"(a[0]), "r"(a[1]), "r"(a[2]), "r"(a[3]), "r"(b[0]), "r"(b[1]));
}

__device__ __forceinline__ float gelu_exact(float x) {
    return 0.5f * x * (1.0f + erff(x * 0.7071067811865476f));
}

__device__ __forceinline__ uint32_t cvta_s(const void* p) {
    return (uint32_t)__cvta_generic_to_shared(p);
}

#define CP16(dst, src) \
    asm volatile("cp.async.cg.shared.global [%0], [%1], 16;\n" :: "r"(dst), "l"(src))

// ---------------- weight transpose + tf32 round + zero-pad ------------------
// in [K][N] row-major  ->  out [Npad][K] row-major, rounded to tf32.
__global__ void transposeW(const float* __restrict__ in, float* __restrict__ outp,
                           int K, int N, int Npad)
{
    __shared__ float t[32][33];
    int nb = blockIdx.x * 32, kb = blockIdx.y * 32;
    int tx = threadIdx.x, ty = threadIdx.y;     // 32 x 8
    #pragma unroll
    for (int p = 0; p < 32; p += 8) {
        int k = kb + ty + p, n = nb + tx;
        float v = (n < N) ? in[(size_t)k * N + n] : 0.f;
        t[ty + p][tx] = to_tf32(v);
    }
    __syncthreads();
    #pragma unroll
    for (int p = 0; p < 32; p += 8) {
        int n = nb + ty + p, k = kb + tx;
        outp[(size_t)n * K + k] = t[tx][ty + p];
    }
}

// ---------------- pipelined tf32 GEMM ---------------------------------------
// C[M,N] = A[M,K] @ Bt[N,K]^T  (+bias, gelu, +resid, optional tf32-round of C)
// CTA 128x128, BK=32, 4-stage cp.async pipeline, 256 thr = 8 warps (2x4),
// warp tile 64x32 of m16n8k8. SMEM stride 36 -> conflict-free fragment loads.
#define BM 128
#define BN 128
#define BK 32
#define STR 36
#define STAGES 4
#define SSTAGE (2 * BM * STR)          // floats per stage (A + B tiles)

__global__ __launch_bounds__(256, 1)
void gemm_tf32p(const float* __restrict__ A, const float* __restrict__ Bt,
                float* __restrict__ C, int M, int N, int K,
                const float* __restrict__ bias, const float* __restrict__ resid,
                int do_gelu, int round_out)
{
    extern __shared__ float smem[];

    const int tid  = threadIdx.x;
    const int lane = tid & 31;
    const int warp = tid >> 5;
    const int wm   = warp >> 2;
    const int wn   = warp & 3;
    const int g    = lane >> 2;
    const int tg   = lane & 3;

    const int m0 = blockIdx.x * BM;
    const int n0 = blockIdx.y * BN;

    float acc[4][4][4];
    #pragma unroll
    for (int mi = 0; mi < 4; mi++)
        #pragma unroll
        for (int ni = 0; ni < 4; ni++)
            #pragma unroll
            for (int r = 0; r < 4; r++) acc[mi][ni][r] = 0.f;

    const int lrow = tid >> 3;            // 0..31
    const int lch  = (tid & 7) * 4;       // 0,4,...,28

    const int KT = K / BK;

    // ---- prologue: preload STAGES-1 k-tiles ----
    #pragma unroll
    for (int s = 0; s < STAGES - 1; s++) {
        float* As = smem + s * SSTAGE;
        float* Bs = As + BM * STR;
        int kt = s * BK;
        #pragma unroll
        for (int p = 0; p < 4; p++) {
            int r = lrow + p * 32;
            CP16(cvta_s(As + r * STR + lch), A  + (size_t)(m0 + r) * K + kt + lch);
        }
        #pragma unroll
        for (int p = 0; p < 4; p++) {
            int r = lrow + p * 32;
            CP16(cvta_s(Bs + r * STR + lch), Bt + (size_t)(n0 + r) * K + kt + lch);
        }
        asm volatile("cp.async.commit_group;\n");
    }

    for (int it = 0; it < KT; it++) {
        asm volatile("cp.async.wait_group %0;\n" :: "n"(STAGES - 2));
        __syncthreads();

        // issue loads for k-tile it+STAGES-1 into buffer (it-1)%STAGES
        int nk = it + STAGES - 1;
        if (nk < KT) {
            float* As = smem + (nk % STAGES) * SSTAGE;
            float* Bs = As + BM * STR;
            int kt = nk * BK;
            #pragma unroll
            for (int p = 0; p < 4; p++) {
                int r = lrow + p * 32;
                CP16(cvta_s(As + r * STR + lch), A  + (size_t)(m0 + r) * K + kt + lch);
            }
            #pragma unroll
            for (int p = 0; p < 4; p++) {
                int r = lrow + p * 32;
                CP16(cvta_s(Bs + r * STR + lch), Bt + (size_t)(n0 + r) * K + kt + lch);
            }
            asm volatile("cp.async.commit_group;\n");
        }

        // compute on buffer it%STAGES
        const float* As = smem + (it % STAGES) * SSTAGE;
        const float* Bs = As + BM * STR;

        #pragma unroll
        for (int kc = 0; kc < 4; kc++) {
            uint32_t af[4][4], bf[4][2];
            #pragma unroll
            for (int mi = 0; mi < 4; mi++) {
                int mb = wm * 64 + mi * 16;
                af[mi][0] = __float_as_uint(As[(mb + g)     * STR + kc * 8 + tg]);
                af[mi][1] = __float_as_uint(As[(mb + g + 8) * STR + kc * 8 + tg]);
                af[mi][2] = __float_as_uint(As[(mb + g)     * STR + kc * 8 + tg + 4]);
                af[mi][3] = __float_as_uint(As[(mb + g + 8) * STR + kc * 8 + tg + 4]);
            }
            #pragma unroll
            for (int ni = 0; ni < 4; ni++) {
                int nb = wn * 32 + ni * 8;
                bf[ni][0] = __float_as_uint(Bs[(nb + g) * STR + kc * 8 + tg]);
                bf[ni][1] = __float_as_uint(Bs[(nb + g) * STR + kc * 8 + tg + 4]);
            }
            #pragma unroll
            for (int mi = 0; mi < 4; mi++)
                #pragma unroll
                for (int ni = 0; ni < 4; ni++)
                    mma_tf32(acc[mi][ni], af[mi], bf[ni]);
        }
    }

    // ---- epilogue ----
    #pragma unroll
    for (int mi = 0; mi < 4; mi++) {
        int row0 = m0 + wm * 64 + mi * 16 + g;
        #pragma unroll
        for (int ni = 0; ni < 4; ni++) {
            int col = n0 + wn * 32 + ni * 8 + tg * 2;
            #pragma unroll
            for (int rr = 0; rr < 2; rr++) {
                int row = row0 + rr * 8;
                #pragma unroll
                for (int j = 0; j < 2; j++) {
                    int c = col + j;
                    if (c < N) {
                        float o = acc[mi][ni][rr * 2 + j];
                        if (bias)     o += bias[c];
                        if (do_gelu)  o = gelu_exact(o);
                        if (resid)    o += resid[(size_t)row * N + c];
                        if (round_out) o = to_tf32(o);
                        C[(size_t)row * N + c] = o;
                    }
                }
            }
        }
    }
}

// ---------------- embedding gather + RMSNorm (tf32-rounded out) -------------
__global__ void embed_rms(const int* __restrict__ x, const float* __restrict__ emb,
                          const float* __restrict__ gamma, float* __restrict__ h1)
{
    int tk = blockIdx.x;
    int b = tk >> 11, t = tk & 2047;
    int id = x[b * S1_ + t];
    const float4* row = (const float4*)(emb + (size_t)id * D_);
    int tid = threadIdx.x;
    float4 v = row[tid];
    float ss = v.x * v.x + v.y * v.y + v.z * v.z + v.w * v.w;
    __shared__ float red[256];
    red[tid] = ss; __syncthreads();
    for (int st = 128; st > 0; st >>= 1) {
        if (tid < st) red[tid] += red[tid + st];
        __syncthreads();
    }
    float scale = 32.0f / fmaxf(sqrtf(red[0]), 1e-12f);
    float4 gv = ((const float4*)gamma)[tid];
    float4 o;
    o.x = to_tf32(v.x * scale * (gv.x + 1.f)); o.y = to_tf32(v.y * scale * (gv.y + 1.f));
    o.z = to_tf32(v.z * scale * (gv.z + 1.f)); o.w = to_tf32(v.w * scale * (gv.w + 1.f));
    ((float4*)(h1 + (size_t)tk * D_))[tid] = o;
}

__global__ void rms_rows(const float* __restrict__ in, const float* __restrict__ gamma,
                         float* __restrict__ outp)
{
    int tk = blockIdx.x;
    int tid = threadIdx.x;
    float4 v = ((const float4*)(in + (size_t)tk * D_))[tid];
    float ss = v.x * v.x + v.y * v.y + v.z * v.z + v.w * v.w;
    __shared__ float red[256];
    red[tid] = ss; __syncthreads();
    for (int st = 128; st > 0; st >>= 1) {
        if (tid < st) red[tid] += red[tid + st];
        __syncthreads();
    }
    float scale = 32.0f / fmaxf(sqrtf(red[0]), 1e-12f);
    float4 gv = ((const float4*)gamma)[tid];
    float4 o;
    o.x = to_tf32(v.x * scale * (gv.x + 1.f)); o.y = to_tf32(v.y * scale * (gv.y + 1.f));
    o.z = to_tf32(v.z * scale * (gv.z + 1.f)); o.w = to_tf32(v.w * scale * (gv.w + 1.f));
    ((float4*)(outp + (size_t)tk * D_))[tid] = o;
}

// ---------------- minGRU chunked linear-recurrence scan ---------------------
__global__ void scan_phase1(const float* __restrict__ hg, float* __restrict__ cb,
                            float* __restrict__ vb, float* __restrict__ Ac,
                            float* __restrict__ Bc)
{
    int gt = blockIdx.x * blockDim.x + threadIdx.x;
    int d = gt & (D_ - 1);
    int chunk = (gt >> 10) & (NCHUNK - 1);
    int b = gt >> 15;
    float Aacc = 1.f, Bacc = 0.f;
    for (int s = 0; s < CLEN; s++) {
        int t = chunk * CLEN + s;
        size_t row = (size_t)(b * S_ + t) * (2 * D_);
        float hid  = hg[row + d];
        float gate = hg[row + D_ + d];
        float c = 1.f / (1.f + expf(gate));
        float z = 1.f / (1.f + expf(-gate));
        float gg = (hid >= 0.f) ? (hid + 0.5f) : (1.f / (1.f + expf(-hid)));
        float v = z * gg;
        size_t o = (size_t)(b * S_ + t) * D_ + d;
        cb[o] = c; vb[o] = v;
        Bacc = c * Bacc + v;
        Aacc *= c;
    }
    int idx = (b * NCHUNK + chunk) * D_ + d;
    Ac[idx] = Aacc; Bc[idx] = Bacc;
}

__global__ void scan_phase2(const float* __restrict__ Ac, const float* __restrict__ Bc,
                            float* __restrict__ carry)
{
    int gt = blockIdx.x * blockDim.x + threadIdx.x;
    int d = gt & (D_ - 1);
    int b = gt >> 10;
    float h = 0.f;
    for (int chunk = 0; chunk < NCHUNK; chunk++) {
        int idx = (b * NCHUNK + chunk) * D_ + d;
        carry[idx] = h;
        h = Ac[idx] * h + Bc[idx];
    }
}

__global__ void scan_phase3(const float* __restrict__ cb, const float* __restrict__ vb,
                            const float* __restrict__ carry, const float* __restrict__ h1,
                            float* __restrict__ h2, float* __restrict__ next_hidden)
{
    int gt = blockIdx.x * blockDim.x + threadIdx.x;
    int d = gt & (D_ - 1);
    int chunk = (gt >> 10) & (NCHUNK - 1);
    int b = gt >> 15;
    float h = carry[(b * NCHUNK + chunk) * D_ + d];
    for (int s = 0; s < CLEN; s++) {
        int t = chunk * CLEN + s;
        size_t o = (size_t)(b * S_ + t) * D_ + d;
        h = cb[o] * h + vb[o];
        h2[o] = to_tf32(h + h1[o]);
        if (t == S_ - 1) next_hidden[b * D_ + d] = h;
    }
}

// ---------------- loss: per-row logsumexp + gather, then mean ---------------
__global__ void loss_rows(const float* __restrict__ logits, const int* __restrict__ x,
                          float* __restrict__ lp)
{
    int tk = blockIdx.x;
    int tid = threadIdx.x;
    const float* row = logits + (size_t)tk * V_;
    int mis  = (int)(((uintptr_t)row >> 2) & 3);
    int head = (4 - mis) & 3;
    int nvec = (V_ - head) >> 2;
    const float4* vrow = (const float4*)(row + head);

    float m = -INFINITY, s = 0.f;
    for (int i = tid; i < head; i += 256) {
        float v = row[i];
        if (v > m) { s = s * expf(m - v) + 1.f; m = v; }
        else       { s += expf(v - m); }
    }
    for (int i = tid; i < nvec; i += 256) {
        float4 v4 = vrow[i];
        float vv[4] = {v4.x, v4.y, v4.z, v4.w};
        #pragma unroll
        for (int j = 0; j < 4; j++) {
            float v = vv[j];
            if (v > m) { s = s * expf(m - v) + 1.f; m = v; }
            else       { s += expf(v - m); }
        }
    }
    for (int i = head + nvec * 4 + tid; i < V_; i += 256) {
        float v = row[i];
        if (v > m) { s = s * expf(m - v) + 1.f; m = v; }
        else       { s += expf(v - m); }
    }

    __shared__ float sm[256], ssum[256];
    sm[tid] = m; ssum[tid] = s; __syncthreads();
    for (int st = 128; st > 0; st >>= 1) {
        if (tid < st) {
            float m2 = sm[tid + st], s2 = ssum[tid + st];
            float M = fmaxf(sm[tid], m2);
            ssum[tid] = ssum[tid] * expf(sm[tid] - M) + s2 * expf(m2 - M);
            sm[tid] = M;
        }
        __syncthreads();
    }
    if (tid == 0) {
        int b = tk >> 11, t = tk & 2047;
        int lab = x[b * S1_ + t + 1];
        lp[tk] = row[lab] - (sm[0] + logf(ssum[0]));
    }
}

__global__ void loss_final(const float* __restrict__ lp, float* __restrict__ outp)
{
    int tid = threadIdx.x;
    float s = 0.f;
    for (int i = tid; i < T_; i += 256) s += lp[i];
    __shared__ float red[256];
    red[tid] = s; __syncthreads();
    for (int st = 128; st > 0; st >>= 1) {
        if (tid < st) red[tid] += red[tid + st];
        __syncthreads();
    }
    if (tid == 0) outp[0] = -red[0] / (float)T_;
}

// ---------------- launch ----------------------------------------------------
extern "C" void kernel_launch(void* const* d_in, const int* in_sizes, int n_in,
                              void* d_out, int out_size)
{
    const int*   x       = (const int*)  d_in[0];
    const float* emb     = (const float*)d_in[1];
    const float* gamma1  = (const float*)d_in[2];
    const float* W_hg    = (const float*)d_in[3];
    const float* W1      = (const float*)d_in[4];
    const float* b1      = (const float*)d_in[5];
    const float* W2      = (const float*)d_in[6];
    const float* b2      = (const float*)d_in[7];
    const float* gamma2  = (const float*)d_in[8];
    const float* Wlog    = (const float*)d_in[9];
    float* out = (float*)d_out;

    float *h1, *hg, *cb, *vb, *Ac, *Bc, *carry, *h2, *mlp1, *h3, *h4, *lp;
    float *whgT, *w1T, *w2T, *wlogT;
    cudaGetSymbolAddress((void**)&h1,    g_h1);
    cudaGetSymbolAddress((void**)&hg,    g_hg);
    cudaGetSymbolAddress((void**)&cb,    g_cb);
    cudaGetSymbolAddress((void**)&vb,    g_vb);
    cudaGetSymbolAddress((void**)&Ac,    g_Ac);
    cudaGetSymbolAddress((void**)&Bc,    g_Bc);
    cudaGetSymbolAddress((void**)&carry, g_carry);
    cudaGetSymbolAddress((void**)&h2,    g_h2);
    cudaGetSymbolAddress((void**)&mlp1,  g_mlp1);
    cudaGetSymbolAddress((void**)&h3,    g_h3);
    cudaGetSymbolAddress((void**)&h4,    g_h4);
    cudaGetSymbolAddress((void**)&lp,    g_lp);
    cudaGetSymbolAddress((void**)&whgT,  g_whgT);
    cudaGetSymbolAddress((void**)&w1T,   g_w1T);
    cudaGetSymbolAddress((void**)&w2T,   g_w2T);
    cudaGetSymbolAddress((void**)&wlogT, g_wlogT);

    static bool attr_set = false;
    if (!attr_set) {
        cudaFuncSetAttribute(gemm_tf32p, cudaFuncAttributeMaxDynamicSharedMemorySize,
                             STAGES * SSTAGE * (int)sizeof(float));
        attr_set = true;
    }
    const int smem_bytes = STAGES * SSTAGE * (int)sizeof(float);

    float* logits      = out + 1;
    float* next_hidden = out + 1 + (size_t)T_ * V_;

    // weight transposes (tf32-rounded, N-padded)
    dim3 tb(32, 8);
    transposeW<<<dim3((2 * D_) / 32, D_ / 32),      tb>>>(W_hg, whgT, D_,     2 * D_, 2 * D_);
    transposeW<<<dim3((4 * D_) / 32, D_ / 32),      tb>>>(W1,   w1T,  D_,     4 * D_, 4 * D_);
    transposeW<<<dim3(D_ / 32, (4 * D_) / 32),      tb>>>(W2,   w2T,  4 * D_, D_,     D_);
    transposeW<<<dim3(VP_ / 32, D_ / 32),           tb>>>(Wlog, wlogT, D_,    V_,     VP_);

    embed_rms<<<T_, 256>>>(x, emb, gamma1, h1);

    // hg = h1 @ W_hg   [4096 x 2048]
    gemm_tf32p<<<dim3(T_ / BM, (2 * D_) / BN), 256, smem_bytes>>>(
        h1, whgT, hg, T_, 2 * D_, D_, nullptr, nullptr, 0, 0);

    scan_phase1<<<(B_ * NCHUNK * D_) / 256, 256>>>(hg, cb, vb, Ac, Bc);
    scan_phase2<<<(B_ * D_) / 256, 256>>>(Ac, Bc, carry);
    scan_phase3<<<(B_ * NCHUNK * D_) / 256, 256>>>(cb, vb, carry, h1, h2, next_hidden);

    // mlp1 = round(gelu(h2 @ W1 + b1))   [4096 x 4096]
    gemm_tf32p<<<dim3(T_ / BM, (4 * D_) / BN), 256, smem_bytes>>>(
        h2, w1T, mlp1, T_, 4 * D_, D_, b1, nullptr, 1, 1);

    // h3 = mlp1 @ W2 + b2 + h2    [4096 x 1024]
    gemm_tf32p<<<dim3(T_ / BM, D_ / BN), 256, smem_bytes>>>(
        mlp1, w2T, h3, T_, D_, 4 * D_, b2, h2, 0, 0);

    rms_rows<<<T_, 256>>>(h3, gamma2, h4);

    // logits = h4 @ W_logits      [4096 x 50257]  (Bt padded to 50304 rows)
    gemm_tf32p<<<dim3(T_ / BM, VP_ / BN), 256, smem_bytes>>>(
        h4, wlogT, logits, T_, V_, D_, nullptr, nullptr, 0, 0);

    loss_rows<<<T_, 256>>>(logits, x, lp);
    loss_final<<<1, 256>>>(lp, out);
}

// round 4
// speedup vs baseline: 2.1021x; 1.4714x over previous
#include <cuda_runtime.h>
#include <cuda_fp16.h>
#include <cstdint>
#include <math.h>

#define D_  1024
#define V_  50257
#define VP_ 50432          // V padded to multiple of 128
#define B_  2
#define S_  2048
#define S1_ 2049
#define T_  4096
#define NCHUNK 32
#define CLEN   64

// ---------------- scratch (static device globals; no runtime allocation) ----
__device__ float  g_h1 [(size_t)T_ * D_];
__device__ __half g_h1h[(size_t)T_ * D_];
__device__ float  g_hg [(size_t)T_ * 2 * D_];
__device__ float  g_Ac [B_ * NCHUNK * D_];
__device__ float  g_Bc [B_ * NCHUNK * D_];
__device__ float  g_carry[B_ * NCHUNK * D_];
__device__ float  g_h2 [(size_t)T_ * D_];
__device__ __half g_h2h[(size_t)T_ * D_];
__device__ __half g_mlp1h[(size_t)T_ * 4 * D_];
__device__ float  g_h3 [(size_t)T_ * D_];
__device__ __half g_h4h[(size_t)T_ * D_];
__device__ float  g_lp [T_];
// transposed (N-major) fp16 weights
__device__ __half g_whgT[(size_t)(2 * D_) * D_];
__device__ __half g_w1T [(size_t)(4 * D_) * D_];
__device__ __half g_w2T [(size_t)D_ * (4 * D_)];
__device__ __half g_wlogT[(size_t)VP_ * D_];

// ---------------- helpers ---------------------------------------------------
__device__ __forceinline__ float gelu_exact(float x) {
    return 0.5f * x * (1.0f + erff(x * 0.7071067811865476f));
}

__device__ __forceinline__ uint32_t cvta_s(const void* p) {
    return (uint32_t)__cvta_generic_to_shared(p);
}

#define CP16(dst, src) \
    asm volatile("cp.async.cg.shared.global [%0], [%1], 16;\n" :: "r"(dst), "l"(src))

__device__ __forceinline__ void mma_f16(float c[4], const uint32_t a[4], const uint32_t b[2]) {
    asm volatile(
        "mma.sync.aligned.m16n8k16.row.col.f32.f16.f16.f32 "
        "{%0,%1,%2,%3}, {%4,%5,%6,%7}, {%8,%9}, {%0,%1,%2,%3};"
        : "+f"(c[0]), "+f"(c[1]), "+f"(c[2]), "+f"(c[3])
        : "r"(a[0]), "r"(a[1]), "r"(a[2]), "r"(a[3]), "r"(b[0]), "r"(b[1]));
}

// ---------------- weight transpose fp32[K][N] -> fp16[Npad][K] --------------
__global__ void transposeW(const float* __restrict__ in, __half* __restrict__ outp,
                           int K, int N, int Npad)
{
    __shared__ float t[32][33];
    int nb = blockIdx.x * 32, kb = blockIdx.y * 32;
    int tx = threadIdx.x, ty = threadIdx.y;     // 32 x 8
    #pragma unroll
    for (int p = 0; p < 32; p += 8) {
        int k = kb + ty + p, n = nb + tx;
        float v = (n < N) ? in[(size_t)k * N + n] : 0.f;
        t[ty + p][tx] = v;
    }
    __syncthreads();
    #pragma unroll
    for (int p = 0; p < 32; p += 8) {
        int n = nb + ty + p, k = kb + tx;
        outp[(size_t)n * K + k] = __float2half_rn(t[tx][ty + p]);
    }
}

// ---------------- pipelined fp16 GEMM ---------------------------------------
// C[M,N] = A[M,K] @ Bt[N,K]^T  (+bias, gelu, +resid; out fp32 or fp16)
// CTA 128x128, BK=32 halves, 4-stage cp.async ring, 256 thr = 8 warps (2x4),
// warp tile 64x32 of m16n8k16. SMEM stride 40 halves -> conflict-free LDS.
#define BM 128
#define BN 128
#define BKH 32
#define STRH 40
#define STAGES 4
#define STG_HALVES (256 * STRH)            // 10240 halves / 20480 B per stage

__global__ __launch_bounds__(256, 1)
void gemm_f16(const __half* __restrict__ A, const __half* __restrict__ Bt,
              void* __restrict__ Cout, int M, int N, int K,
              const float* __restrict__ bias, const float* __restrict__ resid,
              int do_gelu, int out_half)
{
    extern __shared__ __half smemh[];

    const int tid  = threadIdx.x;
    const int lane = tid & 31;
    const int warp = tid >> 5;
    const int wm   = warp >> 2;
    const int wn   = warp & 3;
    const int g    = lane >> 2;
    const int tg   = lane & 3;

    const int m0 = blockIdx.x * BM;
    const int n0 = blockIdx.y * BN;
    const int KT = K / BKH;

    float acc[4][4][4];
    #pragma unroll
    for (int mi = 0; mi < 4; mi++)
        #pragma unroll
        for (int ni = 0; ni < 4; ni++)
            #pragma unroll
            for (int r = 0; r < 4; r++) acc[mi][ni][r] = 0.f;

    // fill: 256 rows (A:0..127, B:128..255) x 4 chunks of 16B
    auto fill = [&](int t) {
        __half* base = smemh + (t & (STAGES - 1)) * STG_HALVES;
        uint32_t sb = cvta_s(base);
        #pragma unroll
        for (int p = 0; p < 4; p++) {
            int idx = tid + p * 256;
            int row = idx >> 2, c = idx & 3;
            const __half* src = (row < 128)
                ? A  + (size_t)(m0 + row) * K + t * BKH + c * 8
                : Bt + (size_t)(n0 + row - 128) * K + t * BKH + c * 8;
            CP16(sb + row * (STRH * 2) + c * 16, src);
        }
        asm volatile("cp.async.commit_group;\n");
    };

    #pragma unroll
    for (int t = 0; t < STAGES - 1; t++) fill(t);

    for (int it = 0; it < KT; it++) {
        asm volatile("cp.async.wait_group %0;\n" :: "n"(STAGES - 2));
        __syncthreads();

        int nk = it + STAGES - 1;
        if (nk < KT) fill(nk);
        else asm volatile("cp.async.commit_group;\n");

        const __half* As = smemh + (it & (STAGES - 1)) * STG_HALVES;
        const __half* Bs = As + 128 * STRH;

        #pragma unroll
        for (int kc = 0; kc < 2; kc++) {
            uint32_t af[4][4], bf[4][2];
            #pragma unroll
            for (int mi = 0; mi < 4; mi++) {
                int mb = wm * 64 + mi * 16;
                const __half* pa = As + (mb + g) * STRH + kc * 16 + 2 * tg;
                af[mi][0] = *(const uint32_t*)(pa);
                af[mi][1] = *(const uint32_t*)(pa + 8 * STRH);
                af[mi][2] = *(const uint32_t*)(pa + 8);
                af[mi][3] = *(const uint32_t*)(pa + 8 * STRH + 8);
            }
            #pragma unroll
            for (int ni = 0; ni < 4; ni++) {
                int nb = wn * 32 + ni * 8;
                const __half* pb = Bs + (nb + g) * STRH + kc * 16 + 2 * tg;
                bf[ni][0] = *(const uint32_t*)(pb);
                bf[ni][1] = *(const uint32_t*)(pb + 8);
            }
            #pragma unroll
            for (int mi = 0; mi < 4; mi++)
                #pragma unroll
                for (int ni = 0; ni < 4; ni++)
                    mma_f16(acc[mi][ni], af[mi], bf[ni]);
        }
    }

    // ---- epilogue ----
    #pragma unroll
    for (int mi = 0; mi < 4; mi++) {
        int row0 = m0 + wm * 64 + mi * 16 + g;
        #pragma unroll
        for (int ni = 0; ni < 4; ni++) {
            int col = n0 + wn * 32 + ni * 8 + tg * 2;
            #pragma unroll
            for (int rr = 0; rr < 2; rr++) {
                int row = row0 + rr * 8;
                float o0 = acc[mi][ni][rr * 2 + 0];
                float o1 = acc[mi][ni][rr * 2 + 1];
                if (bias)    { o0 += bias[col]; o1 += bias[col + 1]; }
                if (do_gelu) { o0 = gelu_exact(o0); o1 = gelu_exact(o1); }
                if (resid)   { o0 += resid[(size_t)row * N + col];
                               o1 += resid[(size_t)row * N + col + 1]; }
                if (out_half) {
                    // N multiple of 128 guaranteed on fp16-out paths
                    *(__half2*)((__half*)Cout + (size_t)row * N + col) =
                        __floats2half2_rn(o0, o1);
                } else {
                    float* C = (float*)Cout;
                    if (col < N)     C[(size_t)row * N + col]     = o0;
                    if (col + 1 < N) C[(size_t)row * N + col + 1] = o1;
                }
            }
        }
    }
}

// ---------------- embedding gather + RMSNorm --------------------------------
__global__ void embed_rms(const int* __restrict__ x, const float* __restrict__ emb,
                          const float* __restrict__ gamma,
                          float* __restrict__ h1, __half* __restrict__ h1h)
{
    int tk = blockIdx.x;
    int b = tk >> 11, t = tk & 2047;
    int id = x[b * S1_ + t];
    const float4* row = (const float4*)(emb + (size_t)id * D_);
    int tid = threadIdx.x;
    float4 v = row[tid];
    float ss = v.x * v.x + v.y * v.y + v.z * v.z + v.w * v.w;
    __shared__ float red[256];
    red[tid] = ss; __syncthreads();
    for (int st = 128; st > 0; st >>= 1) {
        if (tid < st) red[tid] += red[tid + st];
        __syncthreads();
    }
    float scale = 32.0f / fmaxf(sqrtf(red[0]), 1e-12f);
    float4 gv = ((const float4*)gamma)[tid];
    float4 o;
    o.x = v.x * scale * (gv.x + 1.f); o.y = v.y * scale * (gv.y + 1.f);
    o.z = v.z * scale * (gv.z + 1.f); o.w = v.w * scale * (gv.w + 1.f);
    ((float4*)(h1 + (size_t)tk * D_))[tid] = o;
    __half2 p0 = __floats2half2_rn(o.x, o.y);
    __half2 p1 = __floats2half2_rn(o.z, o.w);
    ((__half2*)(h1h + (size_t)tk * D_))[tid * 2]     = p0;
    ((__half2*)(h1h + (size_t)tk * D_))[tid * 2 + 1] = p1;
}

__global__ void rms_rows(const float* __restrict__ in, const float* __restrict__ gamma,
                         __half* __restrict__ outp)
{
    int tk = blockIdx.x;
    int tid = threadIdx.x;
    float4 v = ((const float4*)(in + (size_t)tk * D_))[tid];
    float ss = v.x * v.x + v.y * v.y + v.z * v.z + v.w * v.w;
    __shared__ float red[256];
    red[tid] = ss; __syncthreads();
    for (int st = 128; st > 0; st >>= 1) {
        if (tid < st) red[tid] += red[tid + st];
        __syncthreads();
    }
    float scale = 32.0f / fmaxf(sqrtf(red[0]), 1e-12f);
    float4 gv = ((const float4*)gamma)[tid];
    __half2 p0 = __floats2half2_rn(v.x * scale * (gv.x + 1.f), v.y * scale * (gv.y + 1.f));
    __half2 p1 = __floats2half2_rn(v.z * scale * (gv.z + 1.f), v.w * scale * (gv.w + 1.f));
    ((__half2*)(outp + (size_t)tk * D_))[tid * 2]     = p0;
    ((__half2*)(outp + (size_t)tk * D_))[tid * 2 + 1] = p1;
}

// ---------------- minGRU chunked linear-recurrence scan ---------------------
// h_t = c_t*h_{t-1} + v_t,  c=sigmoid(-gate), v=sigmoid(gate)*g(hidden)
__device__ __forceinline__ void gate_cv(float hid, float gate, float& c, float& v) {
    c = 1.f / (1.f + expf(gate));
    float z = 1.f / (1.f + expf(-gate));
    float gg = (hid >= 0.f) ? (hid + 0.5f) : (1.f / (1.f + expf(-hid)));
    v = z * gg;
}

__global__ void scan_phase1(const float* __restrict__ hg,
                            float* __restrict__ Ac, float* __restrict__ Bc)
{
    int gt = blockIdx.x * blockDim.x + threadIdx.x;
    int d = gt & (D_ - 1);
    int chunk = (gt >> 10) & (NCHUNK - 1);
    int b = gt >> 15;
    float Aacc = 1.f, Bacc = 0.f;
    for (int s = 0; s < CLEN; s++) {
        int t = chunk * CLEN + s;
        size_t row = (size_t)(b * S_ + t) * (2 * D_);
        float c, v;
        gate_cv(hg[row + d], hg[row + D_ + d], c, v);
        Bacc = c * Bacc + v;
        Aacc *= c;
    }
    int idx = (b * NCHUNK + chunk) * D_ + d;
    Ac[idx] = Aacc; Bc[idx] = Bacc;
}

__global__ void scan_phase2(const float* __restrict__ Ac, const float* __restrict__ Bc,
                            float* __restrict__ carry)
{
    int gt = blockIdx.x * blockDim.x + threadIdx.x;
    int d = gt & (D_ - 1);
    int b = gt >> 10;
    float h = 0.f;
    for (int chunk = 0; chunk < NCHUNK; chunk++) {
        int idx = (b * NCHUNK + chunk) * D_ + d;
        carry[idx] = h;
        h = Ac[idx] * h + Bc[idx];
    }
}

__global__ void scan_phase3(const float* __restrict__ hg, const float* __restrict__ carry,
                            const float* __restrict__ h1,
                            float* __restrict__ h2, __half* __restrict__ h2h,
                            float* __restrict__ next_hidden)
{
    int gt = blockIdx.x * blockDim.x + threadIdx.x;
    int d = gt & (D_ - 1);
    int chunk = (gt >> 10) & (NCHUNK - 1);
    int b = gt >> 15;
    float h = carry[(b * NCHUNK + chunk) * D_ + d];
    for (int s = 0; s < CLEN; s++) {
        int t = chunk * CLEN + s;
        size_t row = (size_t)(b * S_ + t) * (2 * D_);
        float c, v;
        gate_cv(hg[row + d], hg[row + D_ + d], c, v);
        h = c * h + v;
        size_t o = (size_t)(b * S_ + t) * D_ + d;
        float hv = h + h1[o];
        h2[o]  = hv;
        h2h[o] = __float2half_rn(hv);
        if (t == S_ - 1) next_hidden[b * D_ + d] = h;
    }
}

// ---------------- loss: per-row logsumexp + gather, then mean ---------------
__global__ void loss_rows(const float* __restrict__ logits, const int* __restrict__ x,
                          float* __restrict__ lp)
{
    int tk = blockIdx.x;
    int tid = threadIdx.x;
    const float* row = logits + (size_t)tk * V_;
    int mis  = (int)(((uintptr_t)row >> 2) & 3);
    int head = (4 - mis) & 3;
    int nvec = (V_ - head) >> 2;
    const float4* vrow = (const float4*)(row + head);

    float m = -INFINITY, s = 0.f;
    for (int i = tid; i < head; i += 256) {
        float v = row[i];
        if (v > m) { s = s * expf(m - v) + 1.f; m = v; }
        else       { s += expf(v - m); }
    }
    for (int i = tid; i < nvec; i += 256) {
        float4 v4 = vrow[i];
        float vv[4] = {v4.x, v4.y, v4.z, v4.w};
        #pragma unroll
        for (int j = 0; j < 4; j++) {
            float v = vv[j];
            if (v > m) { s = s * expf(m - v) + 1.f; m = v; }
            else       { s += expf(v - m); }
        }
    }
    for (int i = head + nvec * 4 + tid; i < V_; i += 256) {
        float v = row[i];
        if (v > m) { s = s * expf(m - v) + 1.f; m = v; }
        else       { s += expf(v - m); }
    }

    __shared__ float sm[256], ssum[256];
    sm[tid] = m; ssum[tid] = s; __syncthreads();
    for (int st = 128; st > 0; st >>= 1) {
        if (tid < st) {
            float m2 = sm[tid + st], s2 = ssum[tid + st];
            float M = fmaxf(sm[tid], m2);
            ssum[tid] = ssum[tid] * expf(sm[tid] - M) + s2 * expf(m2 - M);
            sm[tid] = M;
        }
        __syncthreads();
    }
    if (tid == 0) {
        int b = tk >> 11, t = tk & 2047;
        int lab = x[b * S1_ + t + 1];
        lp[tk] = row[lab] - (sm[0] + logf(ssum[0]));
    }
}

__global__ void loss_final(const float* __restrict__ lp, float* __restrict__ outp)
{
    int tid = threadIdx.x;
    float s = 0.f;
    for (int i = tid; i < T_; i += 256) s += lp[i];
    __shared__ float red[256];
    red[tid] = s; __syncthreads();
    for (int st = 128; st > 0; st >>= 1) {
        if (tid < st) red[tid] += red[tid + st];
        __syncthreads();
    }
    if (tid == 0) outp[0] = -red[0] / (float)T_;
}

// ---------------- launch ----------------------------------------------------
extern "C" void kernel_launch(void* const* d_in, const int* in_sizes, int n_in,
                              void* d_out, int out_size)
{
    const int*   x       = (const int*)  d_in[0];
    const float* emb     = (const float*)d_in[1];
    const float* gamma1  = (const float*)d_in[2];
    const float* W_hg    = (const float*)d_in[3];
    const float* W1      = (const float*)d_in[4];
    const float* b1      = (const float*)d_in[5];
    const float* W2      = (const float*)d_in[6];
    const float* b2      = (const float*)d_in[7];
    const float* gamma2  = (const float*)d_in[8];
    const float* Wlog    = (const float*)d_in[9];
    float* out = (float*)d_out;

    float *h1, *hg, *Ac, *Bc, *carry, *h2, *h3, *lp;
    __half *h1h, *h2h, *mlp1h, *h4h, *whgT, *w1T, *w2T, *wlogT;
    cudaGetSymbolAddress((void**)&h1,    g_h1);
    cudaGetSymbolAddress((void**)&h1h,   g_h1h);
    cudaGetSymbolAddress((void**)&hg,    g_hg);
    cudaGetSymbolAddress((void**)&Ac,    g_Ac);
    cudaGetSymbolAddress((void**)&Bc,    g_Bc);
    cudaGetSymbolAddress((void**)&carry, g_carry);
    cudaGetSymbolAddress((void**)&h2,    g_h2);
    cudaGetSymbolAddress((void**)&h2h,   g_h2h);
    cudaGetSymbolAddress((void**)&mlp1h, g_mlp1h);
    cudaGetSymbolAddress((void**)&h3,    g_h3);
    cudaGetSymbolAddress((void**)&h4h,   g_h4h);
    cudaGetSymbolAddress((void**)&lp,    g_lp);
    cudaGetSymbolAddress((void**)&whgT,  g_whgT);
    cudaGetSymbolAddress((void**)&w1T,   g_w1T);
    cudaGetSymbolAddress((void**)&w2T,   g_w2T);
    cudaGetSymbolAddress((void**)&wlogT, g_wlogT);

    const int smem_bytes = STAGES * STG_HALVES * (int)sizeof(__half);   // 81920
    static bool attr_set = false;
    if (!attr_set) {
        cudaFuncSetAttribute(gemm_f16, cudaFuncAttributeMaxDynamicSharedMemorySize,
                             smem_bytes);
        attr_set = true;
    }

    float* logits      = out + 1;
    float* next_hidden = out + 1 + (size_t)T_ * V_;

    dim3 tb(32, 8);
    transposeW<<<dim3((2 * D_) / 32, D_ / 32), tb>>>(W_hg, whgT, D_,     2 * D_, 2 * D_);
    transposeW<<<dim3((4 * D_) / 32, D_ / 32), tb>>>(W1,   w1T,  D_,     4 * D_, 4 * D_);
    transposeW<<<dim3(D_ / 32, (4 * D_) / 32), tb>>>(W2,   w2T,  4 * D_, D_,     D_);
    transposeW<<<dim3(VP_ / 32, D_ / 32),      tb>>>(Wlog, wlogT, D_,    V_,     VP_);

    embed_rms<<<T_, 256>>>(x, emb, gamma1, h1, h1h);

    // hg = h1 @ W_hg   [4096 x 2048] fp32 out
    gemm_f16<<<dim3(T_ / BM, (2 * D_) / BN), 256, smem_bytes>>>(
        h1h, whgT, hg, T_, 2 * D_, D_, nullptr, nullptr, 0, 0);

    scan_phase1<<<(B_ * NCHUNK * D_) / 256, 256>>>(hg, Ac, Bc);
    scan_phase2<<<(B_ * D_) / 256, 256>>>(Ac, Bc, carry);
    scan_phase3<<<(B_ * NCHUNK * D_) / 256, 256>>>(hg, carry, h1, h2, h2h, next_hidden);

    // mlp1 = gelu(h2 @ W1 + b1)   [4096 x 4096] fp16 out
    gemm_f16<<<dim3(T_ / BM, (4 * D_) / BN), 256, smem_bytes>>>(
        h2h, w1T, mlp1h, T_, 4 * D_, D_, b1, nullptr, 1, 1);

    // h3 = mlp1 @ W2 + b2 + h2    [4096 x 1024] fp32 out
    gemm_f16<<<dim3(T_ / BM, D_ / BN), 256, smem_bytes>>>(
        mlp1h, w2T, h3, T_, D_, 4 * D_, b2, h2, 0, 0);

    rms_rows<<<T_, 256>>>(h3, gamma2, h4h);

    // logits = h4 @ W_logits      [4096 x 50257] fp32 out (Bt padded to 50432)
    gemm_f16<<<dim3(T_ / BM, VP_ / BN), 256, smem_bytes>>>(
        h4h, wlogT, logits, T_, V_, D_, nullptr, nullptr, 0, 0);

    loss_rows<<<T_, 256>>>(logits, x, lp);
    loss_final<<<1, 256>>>(lp, out);
}